// round 15
// baseline (speedup 1.0000x reference)
#include <cuda_runtime.h>
#include <cuda_bf16.h>

// Per-class greedy NMS, round 15 = round 11 + L2::evict_last (legal v8.b32
// form; sm_103a requires 256-bit ld for that modifier). ncu shows the scores
// matrix (15.7MB << 126MB L2) is re-fetched from DRAM every graph replay at
// a DVFS-capped ~560GB/s, and that stream IS the kernel duration. evict_last
// asks L2 to retain it; if honored, replays 2..N stream from L2.
// Bonus: 32B loads halve LDG count. Everything else identical to round 11.

#define MAX_C    80
#define CAPBUF   256
#define NB_FB    2048
#define TOPM     192
#define MCAP     256
#define TRUNC    160
#define K_OUT    100
#define NT       256
#define NBLOCKS  888
#define SCORE_T  0.05f
#define IOU_T    0.5f
#define FINE_LO  0.996f

__device__ unsigned long long g_pairs[MAX_C * CAPBUF];
__device__ unsigned int       g_cnt[MAX_C];   // zero at load; restored each call
__device__ unsigned int       g_bar;
__device__ unsigned int       g_done;

__device__ __forceinline__ unsigned long long make_key(float s, unsigned i) {
    return ((unsigned long long)__float_as_uint(s) << 32)
         | (unsigned long long)(0xFFFFFFFFu - i);
}

struct f8 { float4 a, b; };

// 256-bit read-only load with L2 retain priority (v8.b32 is the only legal
// evict_last ld form on sm_103a)
__device__ __forceinline__ f8 ldg_el8(const float* __restrict__ p) {
    f8 v;
    asm volatile(
        "ld.global.nc.L2::evict_last.v8.b32 {%0,%1,%2,%3,%4,%5,%6,%7}, [%8];"
        : "=f"(v.a.x), "=f"(v.a.y), "=f"(v.a.z), "=f"(v.a.w),
          "=f"(v.b.x), "=f"(v.b.y), "=f"(v.b.z), "=f"(v.b.w)
        : "l"(p));
    return v;
}

__device__ __forceinline__ void emit4(float4 v, int flat0, int C,
                                      unsigned magicC) {
    float m = fmaxf(fmaxf(v.x, v.y), fmaxf(v.z, v.w));
    if (m > FINE_LO) {
        float ss[4] = {v.x, v.y, v.z, v.w};
        #pragma unroll
        for (int u = 0; u < 4; ++u) {
            if (ss[u] > FINE_LO) {
                int flat = flat0 + u;
                unsigned q = (unsigned)(((unsigned long long)(unsigned)flat
                                         * magicC) >> 32);
                int r = flat - (int)q * C;
                if (r < 0)     { --q; r += C; }
                while (r >= C) { ++q; r -= C; }
                unsigned pos = atomicAdd(&g_cnt[r], 1u);
                if (pos < CAPBUF)
                    g_pairs[r * CAPBUF + pos] = make_key(ss[u], q);
            }
        }
    }
}

__device__ __forceinline__ void warp_cutoff(const unsigned int* hist,
                                            int nbucket, int bmin, int* s_b0) {
    const int lane = threadIdx.x;
    int cum = 0, b0 = bmin;
    for (int hi = nbucket - 1; hi >= bmin; hi -= 32) {
        int b = hi - lane;
        int v = (b >= bmin) ? (int)hist[b] : 0;
        int p = v;
        #pragma unroll
        for (int off = 1; off < 32; off <<= 1) {
            int t = __shfl_up_sync(0xFFFFFFFFu, p, off);
            if (lane >= off) p += t;
        }
        unsigned m = __ballot_sync(0xFFFFFFFFu, cum + p >= TOPM);
        if (m) { b0 = hi - (__ffs(m) - 1); break; }
        cum += __shfl_sync(0xFFFFFFFFu, p, 31);
    }
    if (lane == 0) *s_b0 = b0;
}

struct SmemNMS {
    unsigned long long keys[MCAP];
    float4       box[MCAP];
    float        area[MCAP];
    float        score[MCAP];
    unsigned int hist[NB_FB];       // fallback only
    unsigned int keepw[8];
    unsigned int cnt2;
    int          b0, kept, chgr;
};

// rank-scatter over Mfull keys; adjacency/Jacobi truncated to Mp rows.
__device__ __forceinline__ void nms_core(SmemNMS* sm,
                                         const float4* __restrict__ boxes,
                                         int Mfull, int Mp, int tid) {
    const unsigned long long mykey = sm->keys[tid];
    const ulonglong2* __restrict__ k2 = (const ulonglong2*)sm->keys;
    const int jmax = (Mfull + 1) >> 1;    // slots are UNORDERED: scan all keys
    int rank = 0;
    #pragma unroll 4
    for (int j = 0; j < jmax; ++j) {
        ulonglong2 kk = k2[j];
        rank += (kk.x > mykey) ? 1 : 0;
        rank += (kk.y > mykey) ? 1 : 0;
    }
    if (tid < Mfull) {
        int idx = (int)(0xFFFFFFFFu - (unsigned)(mykey & 0xFFFFFFFFull));
        float4 b = __ldg(boxes + idx);
        sm->box[rank]   = b;
        sm->area[rank]  = (b.z - b.x) * (b.w - b.y);
        sm->score[rank] = __uint_as_float((unsigned)(mykey >> 32));
    }
    __syncthreads();

    const int w    = tid >> 5;
    const int lane = tid & 31;
    const int wb   = (w < 4) ? w : 11 - w;   // SMSP-balanced row blocks
    const int row  = wb * 32 + lane;
    const int nwB  = (Mp + 31) >> 5;
    const int wlim = min(wb + 1, nwB);

    const float4 mb  = sm->box[row];
    const float  mya = sm->area[row] + 1e-8f;
    unsigned adjw[8] = {0u,0u,0u,0u,0u,0u,0u,0u};

    // IoU > 0.5  <=>  3*inter > a_i + a_j + 1e-8 (division-free, exact)
    #pragma unroll
    for (int ww = 0; ww < 8; ++ww) {
        if (ww < wlim) {
            unsigned bits = 0u;
            #pragma unroll
            for (int jj = 0; jj < 32; ++jj) {
                int j = ww * 32 + jj;
                float4 cb = sm->box[j];
                float  ca = sm->area[j];
                float ix1 = fmaxf(mb.x, cb.x);
                float iy1 = fmaxf(mb.y, cb.y);
                float ix2 = fminf(mb.z, cb.z);
                float iy2 = fminf(mb.w, cb.w);
                float dx = fmaxf(ix2 - ix1, 0.0f);
                float dy = fmaxf(iy2 - iy1, 0.0f);
                float t = fmaf(3.0f, dx * dy, -(mya + ca));
                if (t > 0.0f && j < row) bits |= (1u << jj);
            }
            adjw[ww] = bits;
        }
    }

    if (tid < 8) {
        int full = Mp >> 5, rem = Mp & 31;
        unsigned v = (tid < full) ? 0xFFFFFFFFu
                   : (tid == full && rem) ? ((1u << rem) - 1u) : 0u;
        sm->keepw[tid] = v;
        if (tid == 0) sm->chgr = -1;
    }
    __syncthreads();

    // Jacobi fixpoint (2 syncs/round): keep[r] = !exists j<r kept & adjacent.
    for (int round = 0; round < MCAP + 2; ++round) {
        unsigned sup = 0u;
        #pragma unroll
        for (int ww = 0; ww < 8; ++ww) sup |= (sm->keepw[ww] & adjw[ww]);
        bool kp = (row < Mp) && (sup == 0u);
        unsigned nw = __ballot_sync(0xFFFFFFFFu, kp);
        __syncthreads();                        // all reads of keepw done
        if (lane == 0 && nw != sm->keepw[wb]) {
            sm->keepw[wb] = nw;
            sm->chgr = round;                   // benign same-value race
        }
        __syncthreads();                        // writes visible
        if (sm->chgr != round) break;           // no word changed -> fixpoint
    }

    if (tid == 0) {
        int tot = 0;
        #pragma unroll
        for (int ww = 0; ww < 8; ++ww) tot += __popc(sm->keepw[ww]);
        sm->kept = tot;
    }
    __syncthreads();
}

__global__ __launch_bounds__(NT, 6)
void fused_nms_kernel(const float* __restrict__ scores,   // [N,C]
                      const float* __restrict__ boxes_f,  // [N,4]
                      float* __restrict__ out,
                      int N, int C, unsigned magicC) {
    const int tid = threadIdx.x;
    const int nwork = (C < MAX_C) ? C : MAX_C;

    // ====== phase 1: strided filter, 2x v8.b32 evict_last loads ======
    {
        const int total  = N * C;
        const int total8 = total >> 3;     // 32B-chunks
        const int T  = gridDim.x * blockDim.x;
        const int j0 = blockIdx.x * blockDim.x + tid;

        for (int b = j0; b < total8; b += 2 * T) {
            int i0 = b, i1 = b + T;
            bool h1 = (i1 < total8);
            f8 v0 = ldg_el8(scores + (long long)i0 * 8);
            f8 v1;
            if (h1) v1 = ldg_el8(scores + (long long)i1 * 8);
            emit4(v0.a, i0 * 8,     C, magicC);
            emit4(v0.b, i0 * 8 + 4, C, magicC);
            if (h1) {
                emit4(v1.a, i1 * 8,     C, magicC);
                emit4(v1.b, i1 * 8 + 4, C, magicC);
            }
        }
        // tail floats (total % 8)
        for (int f = total8 * 8 + j0; f < total; f += T) {
            float s = scores[f];
            if (s > FINE_LO) {
                int i = f / C;
                int c = f - i * C;
                unsigned pos = atomicAdd(&g_cnt[c], 1u);
                if (pos < CAPBUF)
                    g_pairs[c * CAPBUF + pos] = make_key(s, (unsigned)i);
            }
        }
    }

    // ================= global barrier =================
    __threadfence();
    __syncthreads();
    if (tid == 0) atomicAdd(&g_bar, 1u);
    if (blockIdx.x >= nwork) return;
    if (tid == 0) {
        while (*(volatile unsigned*)&g_bar < gridDim.x) __nanosleep(64);
        __threadfence();
    }
    __syncthreads();

    // ================= phase 2: per-class NMS ==========
    const int c = blockIdx.x;
    const float4* __restrict__ boxes = (const float4*)boxes_f;
    __shared__ SmemNMS sm;

    const unsigned cnt = __ldcg(&g_cnt[c]);
    bool fb = (cnt > (unsigned)MCAP);
    int Mp = 0;

    if (!fb) {
        sm.keys[tid] = (tid < (int)cnt)
                     ? __ldcg(&g_pairs[c * CAPBUF + tid]) : 0ull;
        __syncthreads();
        const int Mfull = (int)cnt;
        Mp = min(Mfull, TRUNC);   // exact: insufficient-truncation -> fallback
        nms_core(&sm, boxes, Mfull, Mp, tid);
        if (sm.kept < K_OUT) fb = true;
        __syncthreads();
    }

    if (fb) {   // exact full-range sweep (statistical tail / adversarial only)
        for (int b2 = tid; b2 < NB_FB; b2 += NT) sm.hist[b2] = 0u;
        if (tid == 0) sm.cnt2 = 0u;
        __syncthreads();

        for (int i = tid; i < N; i += NT) {
            float s = scores[(long long)i * C + c];
            if (s > SCORE_T) {
                int b2 = max(min((int)(s * (float)NB_FB), NB_FB - 1), 0);
                atomicAdd(&sm.hist[b2], 1u);
            }
        }
        __syncthreads();
        const int bmin = (int)(SCORE_T * (float)NB_FB);
        if (tid < 32) warp_cutoff(sm.hist, NB_FB, bmin, &sm.b0);
        __syncthreads();
        const int b0 = sm.b0;

        if (tid == 0) sm.cnt2 = 0u;
        __syncthreads();
        for (int i = tid; i < N; i += NT) {
            float s = scores[(long long)i * C + c];
            if (s > SCORE_T) {
                int b2 = max(min((int)(s * (float)NB_FB), NB_FB - 1), 0);
                if (b2 >= b0) {
                    unsigned pos = atomicAdd(&sm.cnt2, 1u);
                    if (pos < MCAP) sm.keys[pos] = make_key(s, (unsigned)i);
                }
            }
        }
        __syncthreads();
        int Mfull = (int)min(sm.cnt2, (unsigned)MCAP);
        for (int i = Mfull + tid; i < MCAP; i += NT) sm.keys[i] = 0ull;
        __syncthreads();
        Mp = Mfull;               // no truncation in the exact path
        nms_core(&sm, boxes, Mfull, Mp, tid);
    }

    // ---- writeout: concat [scores | classes | boxes | valids] ----
    const int CK = C * K_OUT;
    float*  out_scores  = out;
    float*  out_classes = out + CK;
    float4* out_boxes4  = (float4*)(out + 2 * CK);
    float*  out_valid   = out + 6 * CK;

    const int kept_cap = min(sm.kept, K_OUT);

    const int w    = tid >> 5;
    const int lane = tid & 31;
    const int wb   = (w < 4) ? w : 11 - w;
    const int row  = wb * 32 + lane;

    bool mykeep = (row < Mp) && ((sm.keepw[wb] >> lane) & 1u);
    if (mykeep) {
        const unsigned mbm = lane ? ((1u << lane) - 1u) : 0u;
        int pos = 0;
        #pragma unroll
        for (int ww = 0; ww < 8; ++ww) {
            unsigned x = sm.keepw[ww];
            if (ww < wb)       pos += __popc(x);
            else if (ww == wb) pos += __popc(x & mbm);
        }
        if (pos < K_OUT) {
            int o = c * K_OUT + pos;
            out_scores[o] = sm.score[row];
            out_boxes4[o] = sm.box[row];
        }
    }
    if (tid < K_OUT) {
        int o = c * K_OUT + tid;
        out_classes[o] = (float)c;
        out_valid[o]   = (tid < kept_cap) ? 1.0f : 0.0f;
        if (tid >= kept_cap) {
            out_scores[o] = 0.0f;
            out_boxes4[o] = make_float4(0.f, 0.f, 0.f, 0.f);
        }
    }

    // ---- restore global invariants for the next (graph-replayed) call ----
    __syncthreads();
    if (tid == 0) {
        g_cnt[c] = 0u;
        unsigned d = atomicAdd(&g_done, 1u);
        if (d == (unsigned)(nwork - 1)) { g_bar = 0u; g_done = 0u; }
    }
}

extern "C" void kernel_launch(void* const* d_in, const int* in_sizes, int n_in,
                              void* d_out, int out_size) {
    const float* scores = (const float*)d_in[0];  // [N, C]
    const float* boxes  = (const float*)d_in[1];  // [N, 4]
    float* out = (float*)d_out;

    int N = in_sizes[1] / 4;
    int C = in_sizes[0] / N;
    unsigned magicC = (unsigned)((0x100000000ULL + (unsigned)C - 1)
                                 / (unsigned)C);   // ceil(2^32 / C)

    fused_nms_kernel<<<NBLOCKS, NT>>>(scores, boxes, out, N, C, magicC);
}

// round 16
// speedup vs baseline: 1.0013x; 1.0013x over previous
#include <cuda_runtime.h>
#include <cuda_bf16.h>

// Per-class greedy NMS, round 16 = round 11 + boxes carried in the pair
// records. Phase-1 stream is platform-floored (~550-660GB/s regardless of
// machinery: LDG/TMA/occupancy/evict_last all neutral), so this round removes
// the last movable post-barrier latency: the scattered boxes[] gather.
// The filter loads the candidate's box at emit time (hidden under the
// stream) and stores a 32B {key, box} record; phase 2 reads one coalesced
// 32B record per thread and never touches boxes[] on the fast path.

#define MAX_C    80
#define CAPBUF   256
#define NB_FB    2048
#define TOPM     192
#define MCAP     256
#define TRUNC    160
#define K_OUT    100
#define NT       256
#define NBLOCKS  888
#define SCORE_T  0.05f
#define IOU_T    0.5f
#define FINE_LO  0.996f

// 32B records: [2*i] = (key, box.xy bits), [2*i+1] = (box.zw bits, 0)
__device__ ulonglong2        g_pairs[MAX_C * CAPBUF * 2];
__device__ unsigned int      g_cnt[MAX_C];   // zero at load; restored each call
__device__ unsigned int      g_bar;
__device__ unsigned int      g_done;

__device__ __forceinline__ unsigned long long make_key(float s, unsigned i) {
    return ((unsigned long long)__float_as_uint(s) << 32)
         | (unsigned long long)(0xFFFFFFFFu - i);
}

__device__ __forceinline__ void emit4(float4 v, int flat0, int C,
                                      unsigned magicC,
                                      const float4* __restrict__ boxes4) {
    float m = fmaxf(fmaxf(v.x, v.y), fmaxf(v.z, v.w));
    if (m > FINE_LO) {
        float ss[4] = {v.x, v.y, v.z, v.w};
        #pragma unroll
        for (int u = 0; u < 4; ++u) {
            if (ss[u] > FINE_LO) {
                int flat = flat0 + u;
                unsigned q = (unsigned)(((unsigned long long)(unsigned)flat
                                         * magicC) >> 32);
                int r = flat - (int)q * C;
                if (r < 0)     { --q; r += C; }
                while (r >= C) { ++q; r -= C; }
                unsigned pos = atomicAdd(&g_cnt[r], 1u);
                if (pos < CAPBUF) {
                    float4 bx = __ldg(boxes4 + q);   // hidden under stream
                    ulonglong2 r0, r1;
                    r0.x = make_key(ss[u], q);
                    r0.y = ((unsigned long long)__float_as_uint(bx.y) << 32)
                         | (unsigned long long)__float_as_uint(bx.x);
                    r1.x = ((unsigned long long)__float_as_uint(bx.w) << 32)
                         | (unsigned long long)__float_as_uint(bx.z);
                    r1.y = 0ull;
                    long long base = ((long long)r * CAPBUF + pos) * 2;
                    g_pairs[base]     = r0;
                    g_pairs[base + 1] = r1;
                }
            }
        }
    }
}

__device__ __forceinline__ void warp_cutoff(const unsigned int* hist,
                                            int nbucket, int bmin, int* s_b0) {
    const int lane = threadIdx.x;
    int cum = 0, b0 = bmin;
    for (int hi = nbucket - 1; hi >= bmin; hi -= 32) {
        int b = hi - lane;
        int v = (b >= bmin) ? (int)hist[b] : 0;
        int p = v;
        #pragma unroll
        for (int off = 1; off < 32; off <<= 1) {
            int t = __shfl_up_sync(0xFFFFFFFFu, p, off);
            if (lane >= off) p += t;
        }
        unsigned m = __ballot_sync(0xFFFFFFFFu, cum + p >= TOPM);
        if (m) { b0 = hi - (__ffs(m) - 1); break; }
        cum += __shfl_sync(0xFFFFFFFFu, p, 31);
    }
    if (lane == 0) *s_b0 = b0;
}

struct SmemNMS {
    unsigned long long keys[MCAP];
    float4       box[MCAP];
    float        area[MCAP];
    float        score[MCAP];
    unsigned int hist[NB_FB];       // fallback only
    unsigned int keepw[8];
    unsigned int cnt2;
    int          b0, kept, chgr;
};

// rank-scatter (my box arrives in registers) + Mp-bounded balanced triangular
// adjacency + 2-sync Jacobi greedy fixpoint. Block-uniform call; caller must
// have filled sm->keys[0..MCAP) (zeros beyond Mfull) and pass the box that
// belongs to the key in slot tid.
__device__ __forceinline__ void nms_core(SmemNMS* sm, float4 mybox,
                                         int Mfull, int Mp, int tid) {
    const unsigned long long mykey = sm->keys[tid];
    const ulonglong2* __restrict__ k2 = (const ulonglong2*)sm->keys;
    const int jmax = (Mfull + 1) >> 1;    // slots are UNORDERED: scan all keys
    int rank = 0;
    #pragma unroll 4
    for (int j = 0; j < jmax; ++j) {
        ulonglong2 kk = k2[j];
        rank += (kk.x > mykey) ? 1 : 0;
        rank += (kk.y > mykey) ? 1 : 0;
    }
    if (tid < Mfull) {
        sm->box[rank]   = mybox;
        sm->area[rank]  = (mybox.z - mybox.x) * (mybox.w - mybox.y);
        sm->score[rank] = __uint_as_float((unsigned)(mykey >> 32));
    }
    __syncthreads();

    const int w    = tid >> 5;
    const int lane = tid & 31;
    const int wb   = (w < 4) ? w : 11 - w;   // SMSP-balanced row blocks
    const int row  = wb * 32 + lane;
    const int nwB  = (Mp + 31) >> 5;
    const int wlim = min(wb + 1, nwB);

    const float4 mb  = sm->box[row];
    const float  mya = sm->area[row] + 1e-8f;
    unsigned adjw[8] = {0u,0u,0u,0u,0u,0u,0u,0u};

    // IoU > 0.5  <=>  3*inter > a_i + a_j + 1e-8 (division-free, exact)
    #pragma unroll
    for (int ww = 0; ww < 8; ++ww) {
        if (ww < wlim) {
            unsigned bits = 0u;
            #pragma unroll
            for (int jj = 0; jj < 32; ++jj) {
                int j = ww * 32 + jj;
                float4 cb = sm->box[j];
                float  ca = sm->area[j];
                float ix1 = fmaxf(mb.x, cb.x);
                float iy1 = fmaxf(mb.y, cb.y);
                float ix2 = fminf(mb.z, cb.z);
                float iy2 = fminf(mb.w, cb.w);
                float dx = fmaxf(ix2 - ix1, 0.0f);
                float dy = fmaxf(iy2 - iy1, 0.0f);
                float t = fmaf(3.0f, dx * dy, -(mya + ca));
                if (t > 0.0f && j < row) bits |= (1u << jj);
            }
            adjw[ww] = bits;
        }
    }

    if (tid < 8) {
        int full = Mp >> 5, rem = Mp & 31;
        unsigned v = (tid < full) ? 0xFFFFFFFFu
                   : (tid == full && rem) ? ((1u << rem) - 1u) : 0u;
        sm->keepw[tid] = v;
        if (tid == 0) sm->chgr = -1;
    }
    __syncthreads();

    // Jacobi fixpoint (2 syncs/round): keep[r] = !exists j<r kept & adjacent.
    for (int round = 0; round < MCAP + 2; ++round) {
        unsigned sup = 0u;
        #pragma unroll
        for (int ww = 0; ww < 8; ++ww) sup |= (sm->keepw[ww] & adjw[ww]);
        bool kp = (row < Mp) && (sup == 0u);
        unsigned nw = __ballot_sync(0xFFFFFFFFu, kp);
        __syncthreads();                        // all reads of keepw done
        if (lane == 0 && nw != sm->keepw[wb]) {
            sm->keepw[wb] = nw;
            sm->chgr = round;                   // benign same-value race
        }
        __syncthreads();                        // writes visible
        if (sm->chgr != round) break;           // no word changed -> fixpoint
    }

    if (tid == 0) {
        int tot = 0;
        #pragma unroll
        for (int ww = 0; ww < 8; ++ww) tot += __popc(sm->keepw[ww]);
        sm->kept = tot;
    }
    __syncthreads();
}

__global__ __launch_bounds__(NT, 6)
void fused_nms_kernel(const float* __restrict__ scores,   // [N,C]
                      const float* __restrict__ boxes_f,  // [N,4]
                      float* __restrict__ out,
                      int N, int C, unsigned magicC) {
    const int tid = threadIdx.x;
    const int nwork = (C < MAX_C) ? C : MAX_C;
    const float4* __restrict__ boxes = (const float4*)boxes_f;

    // ================= phase 1: strided unroll-4 filter =================
    {
        const int total  = N * C;
        const int total4 = total >> 2;
        const float4* __restrict__ p4 = (const float4*)scores;
        const int T  = gridDim.x * blockDim.x;
        const int j0 = blockIdx.x * blockDim.x + tid;

        for (int b = j0; b < total4; b += 4 * T) {
            float4 v[4];
            bool   h[4];
            #pragma unroll
            for (int q = 0; q < 4; ++q) {
                int idx = b + q * T;
                h[q] = (idx < total4);
                v[q] = h[q] ? p4[idx] : make_float4(0.f, 0.f, 0.f, 0.f);
            }
            #pragma unroll
            for (int q = 0; q < 4; ++q)
                if (h[q]) emit4(v[q], (b + q * T) * 4, C, magicC, boxes);
        }
        for (int f = total4 * 4 + j0; f < total; f += T) {
            float s = scores[f];
            if (s > FINE_LO) {
                int i = f / C;
                int c = f - i * C;
                unsigned pos = atomicAdd(&g_cnt[c], 1u);
                if (pos < CAPBUF) {
                    float4 bx = __ldg(boxes + i);
                    ulonglong2 r0, r1;
                    r0.x = make_key(s, (unsigned)i);
                    r0.y = ((unsigned long long)__float_as_uint(bx.y) << 32)
                         | (unsigned long long)__float_as_uint(bx.x);
                    r1.x = ((unsigned long long)__float_as_uint(bx.w) << 32)
                         | (unsigned long long)__float_as_uint(bx.z);
                    r1.y = 0ull;
                    long long base = ((long long)c * CAPBUF + pos) * 2;
                    g_pairs[base]     = r0;
                    g_pairs[base + 1] = r1;
                }
            }
        }
    }

    // ================= global barrier =================
    __threadfence();
    __syncthreads();
    if (tid == 0) atomicAdd(&g_bar, 1u);
    if (blockIdx.x >= nwork) return;
    if (tid == 0) {
        while (*(volatile unsigned*)&g_bar < gridDim.x) __nanosleep(64);
        __threadfence();
    }
    __syncthreads();

    // ================= phase 2: per-class NMS ==========
    const int c = blockIdx.x;
    __shared__ SmemNMS sm;

    const unsigned cnt = __ldcg(&g_cnt[c]);
    bool fb = (cnt > (unsigned)MCAP);
    int Mp = 0;

    if (!fb) {
        ulonglong2 r0 = make_ulonglong2(0ull, 0ull);
        ulonglong2 r1 = make_ulonglong2(0ull, 0ull);
        if (tid < (int)cnt) {
            long long base = ((long long)c * CAPBUF + tid) * 2;
            r0 = __ldcg(&g_pairs[base]);
            r1 = __ldcg(&g_pairs[base + 1]);
        }
        sm.keys[tid] = r0.x;
        float4 mybox;
        mybox.x = __uint_as_float((unsigned)(r0.y));
        mybox.y = __uint_as_float((unsigned)(r0.y >> 32));
        mybox.z = __uint_as_float((unsigned)(r1.x));
        mybox.w = __uint_as_float((unsigned)(r1.x >> 32));
        __syncthreads();
        const int Mfull = (int)cnt;
        Mp = min(Mfull, TRUNC);   // exact: insufficient-truncation -> fallback
        nms_core(&sm, mybox, Mfull, Mp, tid);
        if (sm.kept < K_OUT) fb = true;
        __syncthreads();
    }

    if (fb) {   // exact full-range sweep (statistical tail / adversarial only)
        for (int b2 = tid; b2 < NB_FB; b2 += NT) sm.hist[b2] = 0u;
        if (tid == 0) sm.cnt2 = 0u;
        __syncthreads();

        for (int i = tid; i < N; i += NT) {
            float s = scores[(long long)i * C + c];
            if (s > SCORE_T) {
                int b2 = max(min((int)(s * (float)NB_FB), NB_FB - 1), 0);
                atomicAdd(&sm.hist[b2], 1u);
            }
        }
        __syncthreads();
        const int bmin = (int)(SCORE_T * (float)NB_FB);
        if (tid < 32) warp_cutoff(sm.hist, NB_FB, bmin, &sm.b0);
        __syncthreads();
        const int b0 = sm.b0;

        if (tid == 0) sm.cnt2 = 0u;
        __syncthreads();
        for (int i = tid; i < N; i += NT) {
            float s = scores[(long long)i * C + c];
            if (s > SCORE_T) {
                int b2 = max(min((int)(s * (float)NB_FB), NB_FB - 1), 0);
                if (b2 >= b0) {
                    unsigned pos = atomicAdd(&sm.cnt2, 1u);
                    if (pos < MCAP) sm.keys[pos] = make_key(s, (unsigned)i);
                }
            }
        }
        __syncthreads();
        int Mfull = (int)min(sm.cnt2, (unsigned)MCAP);
        for (int i = Mfull + tid; i < MCAP; i += NT) sm.keys[i] = 0ull;
        __syncthreads();
        // gather my slot's box (fallback only)
        unsigned long long kk = sm.keys[tid];
        float4 mybox = make_float4(0.f, 0.f, 0.f, 0.f);
        if (kk != 0ull) {
            int idx = (int)(0xFFFFFFFFu - (unsigned)(kk & 0xFFFFFFFFull));
            mybox = __ldg(boxes + idx);
        }
        Mp = Mfull;               // no truncation in the exact path
        nms_core(&sm, mybox, Mfull, Mp, tid);
    }

    // ---- writeout: concat [scores | classes | boxes | valids] ----
    const int CK = C * K_OUT;
    float*  out_scores  = out;
    float*  out_classes = out + CK;
    float4* out_boxes4  = (float4*)(out + 2 * CK);
    float*  out_valid   = out + 6 * CK;

    const int kept_cap = min(sm.kept, K_OUT);

    const int w    = tid >> 5;
    const int lane = tid & 31;
    const int wb   = (w < 4) ? w : 11 - w;
    const int row  = wb * 32 + lane;

    bool mykeep = (row < Mp) && ((sm.keepw[wb] >> lane) & 1u);
    if (mykeep) {
        const unsigned mbm = lane ? ((1u << lane) - 1u) : 0u;
        int pos = 0;
        #pragma unroll
        for (int ww = 0; ww < 8; ++ww) {
            unsigned x = sm.keepw[ww];
            if (ww < wb)       pos += __popc(x);
            else if (ww == wb) pos += __popc(x & mbm);
        }
        if (pos < K_OUT) {
            int o = c * K_OUT + pos;
            out_scores[o] = sm.score[row];
            out_boxes4[o] = sm.box[row];
        }
    }
    if (tid < K_OUT) {
        int o = c * K_OUT + tid;
        out_classes[o] = (float)c;
        out_valid[o]   = (tid < kept_cap) ? 1.0f : 0.0f;
        if (tid >= kept_cap) {
            out_scores[o] = 0.0f;
            out_boxes4[o] = make_float4(0.f, 0.f, 0.f, 0.f);
        }
    }

    // ---- restore global invariants for the next (graph-replayed) call ----
    __syncthreads();
    if (tid == 0) {
        g_cnt[c] = 0u;
        unsigned d = atomicAdd(&g_done, 1u);
        if (d == (unsigned)(nwork - 1)) { g_bar = 0u; g_done = 0u; }
    }
}

extern "C" void kernel_launch(void* const* d_in, const int* in_sizes, int n_in,
                              void* d_out, int out_size) {
    const float* scores = (const float*)d_in[0];  // [N, C]
    const float* boxes  = (const float*)d_in[1];  // [N, 4]
    float* out = (float*)d_out;

    int N = in_sizes[1] / 4;
    int C = in_sizes[0] / N;
    unsigned magicC = (unsigned)((0x100000000ULL + (unsigned)C - 1)
                                 / (unsigned)C);   // ceil(2^32 / C)

    fused_nms_kernel<<<NBLOCKS, NT>>>(scores, boxes, out, N, C, magicC);
}